// round 3
// baseline (speedup 1.0000x reference)
#include <cuda_runtime.h>
#include <cuda_fp16.h>
#include <cstdint>

#define Bb 512
#define Tt 256
#define Hh 1024
#define NCTA 128
#define KCH 64
#define NCHUNK 16          // 1024 / 64
#define NSTG 6
#define STAGE_BYTES 32768  // A tile 16KB + B tile 16KB
#define NTHREADS 256
#define GP 132             // gates smem pitch (floats)
#define SMEM_DYN (1024 + 2048 + NSTG*STAGE_BYTES)

// persistent device state (static allocation — no cudaMalloc)
__device__ __half g_h[Bb * Hh];            // hidden state, fp16 [512,1024]
__device__ __half g_wp[32 * 128 * Hh];     // packed W_hh slabs, fp16
__device__ float  g_xT[Tt * Bb];           // x transposed [T,B]
__device__ int    g_bar;

// ---------------- helpers ----------------
__device__ __forceinline__ uint32_t smem_u32(const void* p) {
    uint32_t a;
    asm("{ .reg .u64 t; cvta.to.shared.u64 t, %1; cvt.u32.u64 %0, t; }" : "=r"(a) : "l"(p));
    return a;
}
__device__ __forceinline__ void cp16(uint32_t dst, const void* src) {
    unsigned long long g = __cvta_generic_to_global(src);
    asm volatile("cp.async.cg.shared.global [%0], [%1], 16;" :: "r"(dst), "l"(g) : "memory");
}
__device__ __forceinline__ void cp_commit() {
    asm volatile("cp.async.commit_group;" ::: "memory");
}
__device__ __forceinline__ void cp_wait4() {
    asm volatile("cp.async.wait_group 4;" ::: "memory");
}
__device__ __forceinline__ void ldsm_x4(uint32_t (&r)[4], uint32_t addr) {
    asm volatile("ldmatrix.sync.aligned.m8n8.x4.shared.b16 {%0,%1,%2,%3}, [%4];"
        : "=r"(r[0]), "=r"(r[1]), "=r"(r[2]), "=r"(r[3]) : "r"(addr));
}
__device__ __forceinline__ void mma16816(float (&d)[4], const uint32_t (&a)[4],
                                         uint32_t b0, uint32_t b1) {
    asm volatile("mma.sync.aligned.m16n8k16.row.col.f32.f16.f16.f32 "
        "{%0,%1,%2,%3}, {%4,%5,%6,%7}, {%8,%9}, {%0,%1,%2,%3};"
        : "+f"(d[0]), "+f"(d[1]), "+f"(d[2]), "+f"(d[3])
        : "r"(a[0]), "r"(a[1]), "r"(a[2]), "r"(a[3]), "r"(b0), "r"(b1));
}
__device__ __forceinline__ float sigm(float x) { return 1.0f / (1.0f + __expf(-x)); }
__device__ __forceinline__ float tanh_(float x) { return 2.0f / (1.0f + __expf(-2.0f * x)) - 1.0f; }

// ---------------- prepack: weights->fp16 slabs, x transpose, h=0, out=b_out ----------------
__global__ void prepack_kernel(const float* __restrict__ x,
                               const float* __restrict__ W_hh,
                               const float* __restrict__ b_out,
                               float* __restrict__ out)
{
    long i = (long)blockIdx.x * blockDim.x + threadIdx.x;
    long stride = (long)gridDim.x * blockDim.x;
    // packed weights: slab jb, row r = gate*32 + jj  ->  W_hh[gate*H + jb*32 + jj, k]
    for (long idx = i; idx < (long)32 * 128 * Hh; idx += stride) {
        int k  = (int)(idx & (Hh - 1));
        int r  = (int)((idx >> 10) & 127);
        int jb = (int)(idx >> 17);
        int g  = r >> 5, jj = r & 31;
        g_wp[idx] = __float2half(W_hh[(long)(g * Hh + jb * 32 + jj) * Hh + k]);
    }
    for (long idx = i; idx < (long)Tt * Bb; idx += stride) {
        int b = (int)(idx & (Bb - 1));
        int t = (int)(idx >> 9);
        g_xT[idx] = x[(long)b * Tt + t];
    }
    for (long idx = i; idx < (long)Bb * Hh; idx += stride)
        g_h[idx] = __float2half(0.0f);
    float bo = b_out[0];
    for (long idx = i; idx < (long)Bb * Tt; idx += stride)
        out[idx] = bo;
    if (i == 0) g_bar = 0;
}

// ---------------- persistent LSTM kernel ----------------
__global__ void __launch_bounds__(NTHREADS, 1) lstm_main(
    const float* __restrict__ W_ih, const float* __restrict__ b_ih,
    const float* __restrict__ b_hh, const float* __restrict__ W_out,
    float* __restrict__ out)
{
    extern __shared__ char smem_raw[];
    uint32_t sraw = smem_u32(smem_raw);
    uint32_t s0 = (sraw + 1023u) & ~1023u;
    char* sm0 = smem_raw + (s0 - sraw);

    const int tid = threadIdx.x;
    const int l   = tid & 31;
    const int w   = tid >> 5;
    const int cta = blockIdx.x;
    const int mb = cta >> 5, jb = cta & 31;
    const int row0 = mb * 128, j0 = jb * 32;

    float* bias_s = (float*)(sm0);           // [128]
    float* wih_s  = (float*)(sm0 + 512);     // [128]
    float* wout_s = (float*)(sm0 + 1024);    // [32]
    const uint32_t TILE0 = s0 + 2048;        // pipeline stages / gates scratch (aliased)
    float* gsm = (float*)(sm0 + 2048);       // gates [128][GP] fp32, aliases stages

    if (tid < 128) {
        int g = tid >> 5, jj = tid & 31;
        int grow = g * Hh + j0 + jj;
        bias_s[tid] = b_ih[grow] + b_hh[grow];
        wih_s[tid]  = W_ih[grow];
    }
    if (tid < 32) wout_s[tid] = W_out[j0 + tid];
    __syncthreads();

    // warp tiling: M0 in {0,32,64,96}, N0 in {0,64}
    const int M0 = (w & 3) * 32;
    const int N0 = (w >> 2) * 64;
    // ldmatrix lane address components
    const int arow0 = M0 + (l & 7) + 8 * ((l >> 3) & 1);   // +16*mi
    const int agrn0 = (l >> 4);                             // + 2*kk
    const int brow0 = N0 + (l & 7) + 8 * (l >> 4);          // +16*p
    const int bgrn0 = (l >> 3) & 1;                         // + 2*kk
    const int l4 = l >> 2, l2 = (l & 3) * 2;

    const char* baseA = (const char*)g_h  + (size_t)row0 * (Hh * 2);
    const char* baseB = (const char*)g_wp + (size_t)jb * 128 * (Hh * 2);

    float c[16];
#pragma unroll
    for (int m = 0; m < 16; m++) c[m] = 0.0f;

    const int row = tid >> 1, half = tid & 1;

#pragma unroll 1
    for (int t = 0; t < Tt; t++) {
        // ---- global barrier: h(t-1) fully written & visible chip-wide ----
        __threadfence();
        __syncthreads();
        if (tid == 0) {
            atomicAdd(&g_bar, 1);
            int target = NCTA * (t + 1);
            while (*(volatile int*)&g_bar < target) { }
        }
        __syncthreads();

        // ---- prologue: load chunks 0..NSTG-2 ----
#pragma unroll
        for (int s = 0; s < NSTG - 1; s++) {
            uint32_t tb = TILE0 + s * STAGE_BYTES;
#pragma unroll
            for (int j = 0; j < 4; j++) {
                int q = tid + 256 * j;
                int r = q >> 3, cb = q & 7;
                uint32_t so = (uint32_t)(r * 128) + (uint32_t)((cb ^ (r & 7)) << 4);
                size_t go = (size_t)r * (Hh * 2) + (size_t)s * (KCH * 2) + (size_t)cb * 16;
                cp16(tb + so,         baseA + go);
                cp16(tb + 16384 + so, baseB + go);
            }
            cp_commit();
        }

        float acc[2][8][4];
#pragma unroll
        for (int mi = 0; mi < 2; mi++)
#pragma unroll
            for (int ni = 0; ni < 8; ni++)
#pragma unroll
                for (int e = 0; e < 4; e++) acc[mi][ni][e] = 0.0f;

        // ---- main K loop, 16 chunks of 64 ----
#pragma unroll 1
        for (int ch = 0; ch < NCHUNK; ch++) {
            cp_wait4();
            __syncthreads();
            // issue loads for chunk ch+NSTG-1
            int nc = ch + NSTG - 1;
            if (nc < NCHUNK) {
                uint32_t tb = TILE0 + (nc % NSTG) * STAGE_BYTES;
#pragma unroll
                for (int j = 0; j < 4; j++) {
                    int q = tid + 256 * j;
                    int r = q >> 3, cb = q & 7;
                    uint32_t so = (uint32_t)(r * 128) + (uint32_t)((cb ^ (r & 7)) << 4);
                    size_t go = (size_t)r * (Hh * 2) + (size_t)nc * (KCH * 2) + (size_t)cb * 16;
                    cp16(tb + so,         baseA + go);
                    cp16(tb + 16384 + so, baseB + go);
                }
            }
            cp_commit();

            uint32_t As = TILE0 + (ch % NSTG) * STAGE_BYTES;
            uint32_t Bs = As + 16384;
#pragma unroll
            for (int kk = 0; kk < 4; kk++) {
                uint32_t a[2][4];
#pragma unroll
                for (int mi = 0; mi < 2; mi++) {
                    int r2 = arow0 + 16 * mi;
                    int gr = 2 * kk + agrn0;
                    ldsm_x4(a[mi], As + (uint32_t)(r2 * 128) + (uint32_t)((gr ^ (r2 & 7)) << 4));
                }
                uint32_t bf[8][2];
#pragma unroll
                for (int p = 0; p < 4; p++) {
                    uint32_t b4[4];
                    int r2 = brow0 + 16 * p;
                    int gr = 2 * kk + bgrn0;
                    ldsm_x4(b4, Bs + (uint32_t)(r2 * 128) + (uint32_t)((gr ^ (r2 & 7)) << 4));
                    bf[2 * p][0] = b4[0]; bf[2 * p][1] = b4[1];
                    bf[2 * p + 1][0] = b4[2]; bf[2 * p + 1][1] = b4[3];
                }
#pragma unroll
                for (int mi = 0; mi < 2; mi++)
#pragma unroll
                    for (int ni = 0; ni < 8; ni++)
                        mma16816(acc[mi][ni], a[mi], bf[ni][0], bf[ni][1]);
            }
        }
        __syncthreads();   // all warps done reading stages before gates alias write

        // ---- store gates to smem (pitch GP=132, float2) ----
#pragma unroll
        for (int mi = 0; mi < 2; mi++)
#pragma unroll
            for (int ni = 0; ni < 8; ni++) {
                int r2 = M0 + mi * 16 + l4;
                int col = N0 + ni * 8 + l2;
                *(float2*)&gsm[r2 * GP + col]       = make_float2(acc[mi][ni][0], acc[mi][ni][1]);
                *(float2*)&gsm[(r2 + 8) * GP + col] = make_float2(acc[mi][ni][2], acc[mi][ni][3]);
            }
        __syncthreads();

        // ---- combine: 256 threads, thread = 2*row + half, 16 jj each ----
        {
            float xv = g_xT[t * Bb + row0 + row];
            int cb0 = row * GP + half * 16;
            float Gi[16], Gg[16], ig[16];
#pragma unroll
            for (int q = 0; q < 4; q++) {
                float4 vi = *(const float4*)&gsm[cb0 + 0  + 4 * q];
                float4 vg = *(const float4*)&gsm[cb0 + 64 + 4 * q];
                Gi[4 * q] = vi.x; Gi[4 * q + 1] = vi.y; Gi[4 * q + 2] = vi.z; Gi[4 * q + 3] = vi.w;
                Gg[4 * q] = vg.x; Gg[4 * q + 1] = vg.y; Gg[4 * q + 2] = vg.z; Gg[4 * q + 3] = vg.w;
            }
#pragma unroll
            for (int m = 0; m < 16; m++) {
                int jj = half * 16 + m;
                float gi = Gi[m] + xv * wih_s[jj]      + bias_s[jj];
                float gg = Gg[m] + xv * wih_s[64 + jj] + bias_s[64 + jj];
                ig[m] = sigm(gi) * tanh_(gg);
            }
            float Gf[16], Go[16];
#pragma unroll
            for (int q = 0; q < 4; q++) {
                float4 vf = *(const float4*)&gsm[cb0 + 32 + 4 * q];
                float4 vo = *(const float4*)&gsm[cb0 + 96 + 4 * q];
                Gf[4 * q] = vf.x; Gf[4 * q + 1] = vf.y; Gf[4 * q + 2] = vf.z; Gf[4 * q + 3] = vf.w;
                Go[4 * q] = vo.x; Go[4 * q + 1] = vo.y; Go[4 * q + 2] = vo.z; Go[4 * q + 3] = vo.w;
            }
            float accy = 0.0f;
            uint32_t hw[8];
#pragma unroll
            for (int p = 0; p < 8; p++) {
                float h2[2];
#pragma unroll
                for (int e = 0; e < 2; e++) {
                    int m = 2 * p + e;
                    int jj = half * 16 + m;
                    float gf = Gf[m] + xv * wih_s[32 + jj] + bias_s[32 + jj];
                    float go = Go[m] + xv * wih_s[96 + jj] + bias_s[96 + jj];
                    float cn = sigm(gf) * c[m] + ig[m];
                    c[m] = cn;
                    float hv = sigm(go) * tanh_(cn);
                    h2[e] = hv;
                    accy += hv * wout_s[jj];
                }
                hw[p] = ((uint32_t)__half_as_ushort(__float2half(h2[1])) << 16)
                      |  (uint32_t)__half_as_ushort(__float2half(h2[0]));
            }
            uint4* dsth = (uint4*)((char*)g_h + ((size_t)(row0 + row) * Hh + j0 + half * 16) * 2);
            dsth[0] = make_uint4(hw[0], hw[1], hw[2], hw[3]);
            dsth[1] = make_uint4(hw[4], hw[5], hw[6], hw[7]);
            float accT = accy + __shfl_xor_sync(0xffffffffu, accy, 1);
            if (half == 0)
                atomicAdd(&out[(size_t)(row0 + row) * Tt + t], accT);
        }
    }
}

extern "C" void kernel_launch(void* const* d_in, const int* in_sizes, int n_in,
                              void* d_out, int out_size) {
    const float* x     = (const float*)d_in[0];
    const float* W_ih  = (const float*)d_in[1];
    const float* W_hh  = (const float*)d_in[2];
    const float* b_ih  = (const float*)d_in[3];
    const float* b_hh  = (const float*)d_in[4];
    const float* W_out = (const float*)d_in[5];
    const float* b_out = (const float*)d_in[6];
    float* out = (float*)d_out;

    cudaFuncSetAttribute(lstm_main, cudaFuncAttributeMaxDynamicSharedMemorySize, SMEM_DYN);

    prepack_kernel<<<2048, 256>>>(x, W_hh, b_out, out);
    lstm_main<<<NCTA, NTHREADS, SMEM_DYN>>>(W_ih, b_ih, b_hh, W_out, out);
}

// round 4
// speedup vs baseline: 1.1036x; 1.1036x over previous
#include <cuda_runtime.h>
#include <cuda_fp16.h>
#include <cstdint>

#define Bb 512
#define Tt 256
#define Hh 1024
#define NCTA 128
#define KCH 64
#define NCHUNK 16          // 1024 / 64
#define NSTG 6
#define STAGE_BYTES 32768  // A tile 16KB + B tile 16KB
#define NTHREADS 512
#define GP 132             // gates smem pitch (floats)
#define SMEM_DYN (1024 + 2048 + NSTG*STAGE_BYTES)

// persistent device state (static allocation — no cudaMalloc)
__device__ __half g_h[Bb * Hh];            // hidden state, fp16 [512,1024]
__device__ __half g_wp[32 * 128 * Hh];     // packed W_hh slabs, fp16
__device__ float  g_xT[Tt * Bb];           // x transposed [T,B]
__device__ int    g_bar;

// ---------------- helpers ----------------
__device__ __forceinline__ uint32_t smem_u32(const void* p) {
    uint32_t a;
    asm("{ .reg .u64 t; cvta.to.shared.u64 t, %1; cvt.u32.u64 %0, t; }" : "=r"(a) : "l"(p));
    return a;
}
__device__ __forceinline__ void cp16(uint32_t dst, const void* src) {
    unsigned long long g = __cvta_generic_to_global(src);
    asm volatile("cp.async.cg.shared.global [%0], [%1], 16;" :: "r"(dst), "l"(g) : "memory");
}
__device__ __forceinline__ void cp_commit() {
    asm volatile("cp.async.commit_group;" ::: "memory");
}
__device__ __forceinline__ void cp_wait4() {
    asm volatile("cp.async.wait_group 4;" ::: "memory");
}
__device__ __forceinline__ void cp_wait0() {
    asm volatile("cp.async.wait_group 0;" ::: "memory");
}
__device__ __forceinline__ void ldsm_x4(uint32_t (&r)[4], uint32_t addr) {
    asm volatile("ldmatrix.sync.aligned.m8n8.x4.shared.b16 {%0,%1,%2,%3}, [%4];"
        : "=r"(r[0]), "=r"(r[1]), "=r"(r[2]), "=r"(r[3]) : "r"(addr));
}
__device__ __forceinline__ void mma16816(float (&d)[4], const uint32_t (&a)[4],
                                         uint32_t b0, uint32_t b1) {
    asm volatile("mma.sync.aligned.m16n8k16.row.col.f32.f16.f16.f32 "
        "{%0,%1,%2,%3}, {%4,%5,%6,%7}, {%8,%9}, {%0,%1,%2,%3};"
        : "+f"(d[0]), "+f"(d[1]), "+f"(d[2]), "+f"(d[3])
        : "r"(a[0]), "r"(a[1]), "r"(a[2]), "r"(a[3]), "r"(b0), "r"(b1));
}
__device__ __forceinline__ float sigm(float x) { return 1.0f / (1.0f + __expf(-x)); }
__device__ __forceinline__ float tanh_(float x) { return 2.0f / (1.0f + __expf(-2.0f * x)) - 1.0f; }

// ---------------- prepack: weights->fp16 slabs, x transpose, h=0, out=b_out ----------------
__global__ void prepack_kernel(const float* __restrict__ x,
                               const float* __restrict__ W_hh,
                               const float* __restrict__ b_out,
                               float* __restrict__ out)
{
    long i = (long)blockIdx.x * blockDim.x + threadIdx.x;
    long stride = (long)gridDim.x * blockDim.x;
    // packed weights: slab jb, row r = gate*32 + jj  ->  W_hh[gate*H + jb*32 + jj, k]
    for (long idx = i; idx < (long)32 * 128 * Hh; idx += stride) {
        int k  = (int)(idx & (Hh - 1));
        int r  = (int)((idx >> 10) & 127);
        int jb = (int)(idx >> 17);
        int g  = r >> 5, jj = r & 31;
        g_wp[idx] = __float2half(W_hh[(long)(g * Hh + jb * 32 + jj) * Hh + k]);
    }
    for (long idx = i; idx < (long)Tt * Bb; idx += stride) {
        int b = (int)(idx & (Bb - 1));
        int t = (int)(idx >> 9);
        g_xT[idx] = x[(long)b * Tt + t];
    }
    for (long idx = i; idx < (long)Bb * Hh; idx += stride)
        g_h[idx] = __float2half(0.0f);
    float bo = b_out[0];
    for (long idx = i; idx < (long)Bb * Tt; idx += stride)
        out[idx] = bo;
    if (i == 0) g_bar = 0;
}

// ---------------- persistent LSTM kernel ----------------
__global__ void __launch_bounds__(NTHREADS, 1) lstm_main(
    const float* __restrict__ W_ih, const float* __restrict__ b_ih,
    const float* __restrict__ b_hh, const float* __restrict__ W_out,
    float* __restrict__ out)
{
    extern __shared__ char smem_raw[];
    uint32_t sraw = smem_u32(smem_raw);
    uint32_t s0 = (sraw + 1023u) & ~1023u;
    char* sm0 = smem_raw + (s0 - sraw);

    const int tid = threadIdx.x;
    const int l   = tid & 31;
    const int w   = tid >> 5;
    const int cta = blockIdx.x;
    const int mb = cta >> 5, jb = cta & 31;
    const int row0 = mb * 128, j0 = jb * 32;

    float* bias_s = (float*)(sm0);           // [128]
    float* wih_s  = (float*)(sm0 + 512);     // [128]
    float* wout_s = (float*)(sm0 + 1024);    // [32]
    const uint32_t TILE0 = s0 + 2048;        // pipeline stages / gates scratch (aliased)
    float* gsm = (float*)(sm0 + 2048);       // gates [128][GP] fp32, aliases stages

    if (tid < 128) {
        int g = tid >> 5, jj = tid & 31;
        int grow = g * Hh + j0 + jj;
        bias_s[tid] = b_ih[grow] + b_hh[grow];
        wih_s[tid]  = W_ih[grow];
    }
    if (tid < 32) wout_s[tid] = W_out[j0 + tid];
    __syncthreads();

    // warp tiling: 16 warps, M0 in {0,32,64,96} (w&3), N0 in {0,32,64,96} (w>>2)
    const int M0 = (w & 3) * 32;
    const int N0 = (w >> 2) * 32;
    // ldmatrix lane address components
    const int arow0 = M0 + (l & 7) + 8 * ((l >> 3) & 1);   // +16*mi
    const int agrn0 = (l >> 4);                             // + 2*kk
    const int brow0 = N0 + (l & 7) + 8 * (l >> 4);          // +16*p
    const int bgrn0 = (l >> 3) & 1;                         // + 2*kk
    const int l4 = l >> 2, l2 = (l & 3) * 2;

    const char* baseA = (const char*)g_h  + (size_t)row0 * (Hh * 2);
    const char* baseB = (const char*)g_wp + (size_t)jb * 128 * (Hh * 2);

    float c[8];
#pragma unroll
    for (int m = 0; m < 8; m++) c[m] = 0.0f;

    const int row = tid >> 2, q4 = tid & 3;   // epilogue mapping: 4 threads per batch row

#pragma unroll 1
    for (int t = 0; t < Tt; t++) {
        // all gsm reads from previous epilogue done before B prefetch clobbers it;
        // threadfence orders this thread's h stores before tid0's barrier arrive
        __threadfence();
        __syncthreads();

        // ---- B (weights) prologue: independent of h, issued BEFORE the barrier ----
#pragma unroll
        for (int s = 0; s < NSTG - 1; s++) {
            uint32_t tb = TILE0 + s * STAGE_BYTES;
#pragma unroll
            for (int j = 0; j < 2; j++) {
                int q = tid + 512 * j;
                int r = q >> 3, cb = q & 7;
                uint32_t so = (uint32_t)(r * 128) + (uint32_t)((cb ^ (r & 7)) << 4);
                size_t go = (size_t)r * (Hh * 2) + (size_t)s * (KCH * 2) + (size_t)cb * 16;
                cp16(tb + 16384 + so, baseB + go);
            }
            cp_commit();
        }

        // ---- global barrier: h(t-1) fully written & visible chip-wide ----
        if (tid == 0) {
            atomicAdd(&g_bar, 1);
            int target = NCTA * (t + 1);
            while (*(volatile int*)&g_bar < target) { }
        }
        __syncthreads();

        // ---- A (h) prologue ----
#pragma unroll
        for (int s = 0; s < NSTG - 1; s++) {
            uint32_t tb = TILE0 + s * STAGE_BYTES;
#pragma unroll
            for (int j = 0; j < 2; j++) {
                int q = tid + 512 * j;
                int r = q >> 3, cb = q & 7;
                uint32_t so = (uint32_t)(r * 128) + (uint32_t)((cb ^ (r & 7)) << 4);
                size_t go = (size_t)r * (Hh * 2) + (size_t)s * (KCH * 2) + (size_t)cb * 16;
                cp16(tb + so, baseA + go);
            }
            cp_commit();
        }

        float acc[2][4][4];
#pragma unroll
        for (int mi = 0; mi < 2; mi++)
#pragma unroll
            for (int ni = 0; ni < 4; ni++)
#pragma unroll
                for (int e = 0; e < 4; e++) acc[mi][ni][e] = 0.0f;

        // ---- main K loop, 16 chunks of 64, register-double-buffered fragments ----
#pragma unroll 1
        for (int ch = 0; ch < NCHUNK; ch++) {
            cp_wait4();
            __syncthreads();
            // issue loads for chunk ch+NSTG-1 (A+B together, one group)
            int nc = ch + NSTG - 1;
            if (nc < NCHUNK) {
                uint32_t tb = TILE0 + (nc % NSTG) * STAGE_BYTES;
#pragma unroll
                for (int j = 0; j < 2; j++) {
                    int q = tid + 512 * j;
                    int r = q >> 3, cb = q & 7;
                    uint32_t so = (uint32_t)(r * 128) + (uint32_t)((cb ^ (r & 7)) << 4);
                    size_t go = (size_t)r * (Hh * 2) + (size_t)nc * (KCH * 2) + (size_t)cb * 16;
                    cp16(tb + so,         baseA + go);
                    cp16(tb + 16384 + so, baseB + go);
                }
            }
            cp_commit();

            uint32_t As = TILE0 + (ch % NSTG) * STAGE_BYTES;
            uint32_t Bs = As + 16384;

            uint32_t a[2][2][4];   // [buf][mi][4]
            uint32_t bf[2][4][2];  // [buf][ni][2]
            // prefetch kk=0
#pragma unroll
            for (int mi = 0; mi < 2; mi++) {
                int r2 = arow0 + 16 * mi;
                ldsm_x4(a[0][mi], As + (uint32_t)(r2 * 128) + (uint32_t)((agrn0 ^ (r2 & 7)) << 4));
            }
#pragma unroll
            for (int p = 0; p < 2; p++) {
                uint32_t b4[4];
                int r2 = brow0 + 16 * p;
                ldsm_x4(b4, Bs + (uint32_t)(r2 * 128) + (uint32_t)((bgrn0 ^ (r2 & 7)) << 4));
                bf[0][2 * p][0] = b4[0]; bf[0][2 * p][1] = b4[1];
                bf[0][2 * p + 1][0] = b4[2]; bf[0][2 * p + 1][1] = b4[3];
            }
#pragma unroll
            for (int kk = 0; kk < 4; kk++) {
                int cur = kk & 1, nxt = cur ^ 1;
                if (kk < 3) {
                    int gr_a = 2 * (kk + 1) + agrn0;
                    int gr_b = 2 * (kk + 1) + bgrn0;
#pragma unroll
                    for (int mi = 0; mi < 2; mi++) {
                        int r2 = arow0 + 16 * mi;
                        ldsm_x4(a[nxt][mi], As + (uint32_t)(r2 * 128) + (uint32_t)((gr_a ^ (r2 & 7)) << 4));
                    }
#pragma unroll
                    for (int p = 0; p < 2; p++) {
                        uint32_t b4[4];
                        int r2 = brow0 + 16 * p;
                        ldsm_x4(b4, Bs + (uint32_t)(r2 * 128) + (uint32_t)((gr_b ^ (r2 & 7)) << 4));
                        bf[nxt][2 * p][0] = b4[0]; bf[nxt][2 * p][1] = b4[1];
                        bf[nxt][2 * p + 1][0] = b4[2]; bf[nxt][2 * p + 1][1] = b4[3];
                    }
                }
#pragma unroll
                for (int mi = 0; mi < 2; mi++)
#pragma unroll
                    for (int ni = 0; ni < 4; ni++)
                        mma16816(acc[mi][ni], a[cur][mi], bf[cur][ni][0], bf[cur][ni][1]);
            }
        }
        cp_wait0();
        __syncthreads();   // all warps done reading stages before gates alias write

        // ---- store gates to smem (pitch GP=132, float2) ----
#pragma unroll
        for (int mi = 0; mi < 2; mi++)
#pragma unroll
            for (int ni = 0; ni < 4; ni++) {
                int r2 = M0 + mi * 16 + l4;
                int col = N0 + ni * 8 + l2;
                *(float2*)&gsm[r2 * GP + col]       = make_float2(acc[mi][ni][0], acc[mi][ni][1]);
                *(float2*)&gsm[(r2 + 8) * GP + col] = make_float2(acc[mi][ni][2], acc[mi][ni][3]);
            }
        __syncthreads();

        // ---- combine: 512 threads, thread = 4*row + q4, 8 jj each ----
        {
            float xv = g_xT[t * Bb + row0 + row];
            int cb0 = row * GP + q4 * 8;
            float Gi[8], Gg[8], ig[8];
#pragma unroll
            for (int qq = 0; qq < 2; qq++) {
                float4 vi = *(const float4*)&gsm[cb0 + 0  + 4 * qq];
                float4 vg = *(const float4*)&gsm[cb0 + 64 + 4 * qq];
                Gi[4 * qq] = vi.x; Gi[4 * qq + 1] = vi.y; Gi[4 * qq + 2] = vi.z; Gi[4 * qq + 3] = vi.w;
                Gg[4 * qq] = vg.x; Gg[4 * qq + 1] = vg.y; Gg[4 * qq + 2] = vg.z; Gg[4 * qq + 3] = vg.w;
            }
#pragma unroll
            for (int m = 0; m < 8; m++) {
                int jj = q4 * 8 + m;
                float gi = Gi[m] + xv * wih_s[jj]      + bias_s[jj];
                float gg = Gg[m] + xv * wih_s[64 + jj] + bias_s[64 + jj];
                ig[m] = sigm(gi) * tanh_(gg);
            }
            float Gf[8], Go[8];
#pragma unroll
            for (int qq = 0; qq < 2; qq++) {
                float4 vf = *(const float4*)&gsm[cb0 + 32 + 4 * qq];
                float4 vo = *(const float4*)&gsm[cb0 + 96 + 4 * qq];
                Gf[4 * qq] = vf.x; Gf[4 * qq + 1] = vf.y; Gf[4 * qq + 2] = vf.z; Gf[4 * qq + 3] = vf.w;
                Go[4 * qq] = vo.x; Go[4 * qq + 1] = vo.y; Go[4 * qq + 2] = vo.z; Go[4 * qq + 3] = vo.w;
            }
            float accy = 0.0f;
            uint32_t hw[4];
#pragma unroll
            for (int p = 0; p < 4; p++) {
                float h2[2];
#pragma unroll
                for (int e = 0; e < 2; e++) {
                    int m = 2 * p + e;
                    int jj = q4 * 8 + m;
                    float gf = Gf[m] + xv * wih_s[32 + jj] + bias_s[32 + jj];
                    float go = Go[m] + xv * wih_s[96 + jj] + bias_s[96 + jj];
                    float cn = sigm(gf) * c[m] + ig[m];
                    c[m] = cn;
                    float hv = sigm(go) * tanh_(cn);
                    h2[e] = hv;
                    accy += hv * wout_s[jj];
                }
                hw[p] = ((uint32_t)__half_as_ushort(__float2half(h2[1])) << 16)
                      |  (uint32_t)__half_as_ushort(__float2half(h2[0]));
            }
            uint4* dsth = (uint4*)((char*)g_h + ((size_t)(row0 + row) * Hh + j0 + q4 * 8) * 2);
            dsth[0] = make_uint4(hw[0], hw[1], hw[2], hw[3]);
            // reduce head partial over the 4 threads of this row (adjacent lanes)
            float accT = accy + __shfl_xor_sync(0xffffffffu, accy, 1);
            accT += __shfl_xor_sync(0xffffffffu, accT, 2);
            if (q4 == 0)
                atomicAdd(&out[(size_t)(row0 + row) * Tt + t], accT);
        }
    }
}

extern "C" void kernel_launch(void* const* d_in, const int* in_sizes, int n_in,
                              void* d_out, int out_size) {
    const float* x     = (const float*)d_in[0];
    const float* W_ih  = (const float*)d_in[1];
    const float* W_hh  = (const float*)d_in[2];
    const float* b_ih  = (const float*)d_in[3];
    const float* b_hh  = (const float*)d_in[4];
    const float* W_out = (const float*)d_in[5];
    const float* b_out = (const float*)d_in[6];
    float* out = (float*)d_out;

    cudaFuncSetAttribute(lstm_main, cudaFuncAttributeMaxDynamicSharedMemorySize, SMEM_DYN);

    prepack_kernel<<<2048, 256>>>(x, W_hh, b_out, out);
    lstm_main<<<NCTA, NTHREADS, SMEM_DYN>>>(W_ih, b_ih, b_hh, W_out, out);
}